// round 10
// baseline (speedup 1.0000x reference)
#include <cuda_runtime.h>
#include <cuda_bf16.h>
#include <cstdint>

#define M_CONST   100
#define GROUPS    25      // M/4 float4 groups per row
#define ROWS_ITER 10      // rows per block iteration (250 active threads)
#define ACTIVE    (GROUPS * ROWS_ITER)

__device__ __forceinline__ float ex2_(float x) {
    float r; asm("ex2.approx.f32 %0, %1;" : "=f"(r) : "f"(x)); return r;
}
__device__ __forceinline__ float rcp_(float x) {
    float r; asm("rcp.approx.f32 %0, %1;" : "=f"(r) : "f"(x)); return r;
}

// rsqrt WITHOUT MUFU: magic-constant seed + 2 Newton iterations.
// Rel err ~5e-6 — well inside the 1e-3 output gate. 7 FMA-pipe + 2 ALU ops.
__device__ __forceinline__ float rsqrt_fma(float d) {
    const float h = 0.5f * d;
    uint32_t i = __float_as_uint(d);
    i = 0x5f3759dfu - (i >> 1);
    float y = __uint_as_float(i);
    float t = h * y;
    y = y * fmaf(-t, y, 1.5f);     // Newton 1
    t = h * y;
    y = y * fmaf(-t, y, 1.5f);     // Newton 2
    return y;
}

#define NEG_HALF_LOG2E -0.7213475204444817f  // -0.5*log2(e): exp -> ex2
#define INV_TWO_PI      0.15915494309189535f

// basis_sigma is diagonal (reference: vmap(diag)(var)):
//   det  = c00*c11 - s01^2
//   quad = (c11 dx^2 - 2 s01 dx dy + c00 dy^2) / det
// Thread t (<250): basis group g = t%25 (elements 4g..4g+3, cached in regs),
// row slot t/25; grid-strides over rows. ONE MUFU (EX2) per element.
__global__ __launch_bounds__(256) void ContinuousSoftmax_kernel(
    const float* __restrict__ theta,        // [N,6]
    const float* __restrict__ basis_mu,     // [M,2]
    const float* __restrict__ basis_sigma,  // [M,2,2] diagonal
    float* __restrict__ out,                // [N,M]
    int N)
{
    const int tid = threadIdx.x;
    if (tid >= ACTIVE) return;
    const int r_local = tid / GROUPS;
    const int g       = tid - r_local * GROUPS;   // 0..24

    // ---- one-time: cache this thread's 4 basis entries in registers ----
    const float4* bm = reinterpret_cast<const float4*>(basis_mu) + 2 * g;
    const float4  m01 = bm[0];
    const float4  m23 = bm[1];
    const float4* bs = reinterpret_cast<const float4*>(basis_sigma) + 4 * g;
    const float4  sg0 = bs[0], sg1 = bs[1], sg2 = bs[2], sg3 = bs[3];

    const float nbm0[4] = {-m01.x, -m01.z, -m23.x, -m23.z};
    const float nbm1[4] = {-m01.y, -m01.w, -m23.y, -m23.w};
    const float av[4]   = {sg0.x, sg1.x, sg2.x, sg3.x};   // diag var_x
    const float bv[4]   = {sg0.w, sg1.w, sg2.w, sg3.w};   // diag var_y

    const int stride = gridDim.x * ROWS_ITER;
    const float2* th2 = reinterpret_cast<const float2*>(theta);

    for (int n = blockIdx.x * ROWS_ITER + r_local; n < N; n += stride) {
        // theta row: 3x LDG.64 (L1-broadcast among the 25 threads sharing n)
        const float2 e  = th2[(size_t)n * 3 + 0];
        const float2 q0 = th2[(size_t)n * 3 + 1];
        const float2 q1 = th2[(size_t)n * 3 + 2];

        // Sigma = 0.5*(Pinv+Pinv^T), P = -2*[[q0.x,q0.y],[q1.x,q1.y]]
        const float d     = q0.x * q1.y - q0.y * q1.x;
        const float r     = rcp_(d);                      // MUFU.RCP (per row)
        const float u01   = -0.5f * (q0.y + q1.x);
        const float m0p   = q1.y * e.x + u01 * e.y;       // overlap RCP latency
        const float m1p   = u01 * e.x + q0.x * e.y;
        const float inv   = -0.5f * r;                    // = -1/(2d)
        const float s00   = q1.y * inv;
        const float s11   = q0.x * inv;
        const float s01   = u01  * inv;
        const float mu0   = m0p * inv;
        const float mu1   = m1p * inv;
        const float ns01q = -(s01 * s01);                 // -s01^2
        const float s01_2 = s01 + s01;                    // 2*s01

        float res[4];
        #pragma unroll
        for (int k = 0; k < 4; ++k) {
            const float c00 = s00 + av[k];
            const float c11 = s11 + bv[k];
            const float dx  = mu0 + nbm0[k];
            const float dy  = mu1 + nbm1[k];
            const float det = fmaf(c00, c11, ns01q);
            const float rs  = rsqrt_fma(det);             // FMA-pipe rsqrt
            const float t     = s01_2 * dy;
            const float inner = fmaf(c11, dx, -t);        // c11*dx - 2*s01*dy
            const float v     = dx * inner;
            const float u     = c00 * dy;
            const float num   = fmaf(u, dy, v);           // quad numerator
            const float numc  = num * NEG_HALF_LOG2E;     // FMUL-imm
            const float arg   = (numc * rs) * rs;         // /det via rs^2
            const float scl   = rs * INV_TWO_PI;          // FMUL-imm
            res[k] = ex2_(arg) * scl;                     // MUFU.EX2 (the only
                                                          //  per-element MUFU)
        }
        float4 v4 = make_float4(res[0], res[1], res[2], res[3]);
        *reinterpret_cast<float4*>(out + (size_t)n * M_CONST + 4 * g) = v4;
    }
}

extern "C" void kernel_launch(void* const* d_in, const int* in_sizes, int n_in,
                              void* d_out, int out_size) {
    const float* theta       = (const float*)d_in[0];
    const float* basis_mu    = (const float*)d_in[1];
    const float* basis_sigma = (const float*)d_in[2];
    float* out = (float*)d_out;

    const int N = in_sizes[0] / 6;

    const int threads = 256;
    const int needed  = (N + ROWS_ITER - 1) / ROWS_ITER;
    int blocks = 1536;
    if (blocks > needed) blocks = needed;
    ContinuousSoftmax_kernel<<<blocks, threads>>>(theta, basis_mu, basis_sigma,
                                                  out, N);
}

// round 11
// speedup vs baseline: 1.6094x; 1.6094x over previous
#include <cuda_runtime.h>
#include <cuda_bf16.h>
#include <cstdint>

#define M_CONST    100
#define GROUPS     25     // M/4 float4 groups per row
#define ROWS_ITER  10     // rows per loop iteration (250 active threads)
#define ACTIVE     (GROUPS * ROWS_ITER)
#define CHUNK_ROWS 90     // contiguous rows per block (9 iterations)

__device__ __forceinline__ float ex2_(float x) {
    float r; asm("ex2.approx.f32 %0, %1;" : "=f"(r) : "f"(x)); return r;
}
__device__ __forceinline__ float rcp_(float x) {
    float r; asm("rcp.approx.f32 %0, %1;" : "=f"(r) : "f"(x)); return r;
}

#define NEG_HALF_LOG2E -0.7213475204444817f  // -0.5*log2(e): exp -> ex2
#define INV_TWO_PI      0.15915494309189535f

// basis_sigma is diagonal (reference: vmap(diag)(var)):
//   det  = c00*c11 - s01^2
//   quad = (c11 dx^2 - 2 s01 dx dy + c00 dy^2) / det
// Block owns a contiguous 90-row chunk; its theta slice is staged into smem
// in one parallel burst (L2 latency paid once, fully overlapped), so the hot
// loop has ZERO global loads — only LDS broadcasts + math + one STG.128.
__global__ __launch_bounds__(256) void ContinuousSoftmax_kernel(
    const float* __restrict__ theta,        // [N,6]
    const float* __restrict__ basis_mu,     // [M,2]
    const float* __restrict__ basis_sigma,  // [M,2,2] diagonal
    float* __restrict__ out,                // [N,M]
    int N)
{
    __shared__ float sth[CHUNK_ROWS * 6];

    const int tid  = threadIdx.x;
    const int row0 = blockIdx.x * CHUNK_ROWS;
    const int nrows = (N - row0 < CHUNK_ROWS) ? (N - row0) : CHUNK_ROWS;

    // ---- stage this block's theta slice (coalesced, high MLP) ----
    for (int i = tid; i < nrows * 6; i += 256)
        sth[i] = theta[(size_t)row0 * 6 + i];
    __syncthreads();

    if (tid >= ACTIVE) return;
    const int r_local = tid / GROUPS;             // 0..9
    const int g       = tid - r_local * GROUPS;   // 0..24

    // ---- one-time: cache this thread's 4 basis entries in registers ----
    const float4* bm = reinterpret_cast<const float4*>(basis_mu) + 2 * g;
    const float4  m01 = bm[0];
    const float4  m23 = bm[1];
    const float4* bs = reinterpret_cast<const float4*>(basis_sigma) + 4 * g;
    const float4  sg0 = bs[0], sg1 = bs[1], sg2 = bs[2], sg3 = bs[3];

    const float nbm0[4] = {-m01.x, -m01.z, -m23.x, -m23.z};
    const float nbm1[4] = {-m01.y, -m01.w, -m23.y, -m23.w};
    const float av[4]   = {sg0.x, sg1.x, sg2.x, sg3.x};   // diag var_x
    const float bv[4]   = {sg0.w, sg1.w, sg2.w, sg3.w};   // diag var_y

    const float2* sth2 = reinterpret_cast<const float2*>(sth);

    for (int rr = r_local; rr < nrows; rr += ROWS_ITER) {
        // theta from shared (29-cyc LDS broadcast across the 25 threads)
        const float2 e  = sth2[rr * 3 + 0];
        const float2 q0 = sth2[rr * 3 + 1];
        const float2 q1 = sth2[rr * 3 + 2];

        // Sigma = 0.5*(Pinv+Pinv^T), P = -2*[[q0.x,q0.y],[q1.x,q1.y]]
        const float d     = q0.x * q1.y - q0.y * q1.x;
        const float r     = rcp_(d);                      // MUFU.RCP (per row)
        const float u01   = -0.5f * (q0.y + q1.x);
        const float m0p   = q1.y * e.x + u01 * e.y;       // overlap RCP latency
        const float m1p   = u01 * e.x + q0.x * e.y;
        const float inv   = -0.5f * r;                    // = -1/(2d)
        const float s00   = q1.y * inv;
        const float s11   = q0.x * inv;
        const float s01   = u01  * inv;
        const float mu0   = m0p * inv;
        const float mu1   = m1p * inv;
        const float ns01q = -(s01 * s01);                 // -s01^2
        const float s01_2 = s01 + s01;                    // 2*s01

        // dets + RSQs first: all 4 MUFUs in flight before the numerators
        float det[4], rs[4];
        #pragma unroll
        for (int k = 0; k < 4; ++k) {
            det[k] = fmaf(s00 + av[k], s11 + bv[k], ns01q);
            rs[k]  = rsqrtf(det[k]);                      // MUFU.RSQ
        }

        float res[4];
        #pragma unroll
        for (int k = 0; k < 4; ++k) {
            const float c00 = s00 + av[k];
            const float c11 = s11 + bv[k];
            const float dx  = mu0 + nbm0[k];
            const float dy  = mu1 + nbm1[k];
            const float t     = s01_2 * dy;
            const float inner = fmaf(c11, dx, -t);        // c11*dx - 2*s01*dy
            const float v     = dx * inner;
            const float u     = c00 * dy;
            const float num   = fmaf(u, dy, v);           // quad numerator
            const float numc  = num * NEG_HALF_LOG2E;     // FMUL-imm
            const float arg   = (numc * rs[k]) * rs[k];   // /det via rs^2
            const float scl   = rs[k] * INV_TWO_PI;       // FMUL-imm
            res[k] = ex2_(arg) * scl;                     // MUFU.EX2
        }
        float4 v4 = make_float4(res[0], res[1], res[2], res[3]);
        *reinterpret_cast<float4*>(out + (size_t)(row0 + rr) * M_CONST + 4 * g) = v4;
    }
}

extern "C" void kernel_launch(void* const* d_in, const int* in_sizes, int n_in,
                              void* d_out, int out_size) {
    const float* theta       = (const float*)d_in[0];
    const float* basis_mu    = (const float*)d_in[1];
    const float* basis_sigma = (const float*)d_in[2];
    float* out = (float*)d_out;

    const int N = in_sizes[0] / 6;

    const int threads = 256;
    const int blocks  = (N + CHUNK_ROWS - 1) / CHUNK_ROWS;   // 1457 for N=131072
    ContinuousSoftmax_kernel<<<blocks, threads>>>(theta, basis_mu, basis_sigma,
                                                  out, N);
}

// round 12
// speedup vs baseline: 1.7863x; 1.1099x over previous
#include <cuda_runtime.h>
#include <cuda_bf16.h>
#include <cstdint>

#define M_CONST    100
#define GROUPS     25     // M/4 float4 groups per row
#define ROWS_ITER  10     // rows per loop iteration (250 active threads)
#define ACTIVE     (GROUPS * ROWS_ITER)
#define CHUNK_ROWS 90     // contiguous rows per block (9 hot iterations)

__device__ __forceinline__ float ex2_(float x) {
    float r; asm("ex2.approx.f32 %0, %1;" : "=f"(r) : "f"(x)); return r;
}
__device__ __forceinline__ float rcp_(float x) {
    float r; asm("rcp.approx.f32 %0, %1;" : "=f"(r) : "f"(x)); return r;
}

#define SQRT_HL2E  0.8493218002880191f   // sqrt(0.5*log2(e)) folded into dx,dy
#define INV_TWO_PI 0.15915494309189535f

// basis_sigma is diagonal (reference: vmap(diag)(var)).
// All per-row work (2x2 inverse, Mu, derived constants) is hoisted into a
// block prologue (threads 0..89 in parallel, one RCP each); the hot loop is
// pure per-element math: LDS -> det -> RSQ -> num -> EX2 -> STG.128.
//   det  = c00*c11 - s01^2
//   arg  = -(num' * rs) * rs,  num' built from pre-scaled dx' = sqrt(K)*dx
__global__ __launch_bounds__(256) void ContinuousSoftmax_kernel(
    const float* __restrict__ theta,        // [N,6]
    const float* __restrict__ basis_mu,     // [M,2]
    const float* __restrict__ basis_sigma,  // [M,2,2] diagonal
    float* __restrict__ out,                // [N,M]
    int N)
{
    __shared__ float4 spA[CHUNK_ROWS];   // s00, s11, mu0', mu1'
    __shared__ float2 spB[CHUNK_ROWS];   // ns01q, s01_2

    const int tid   = threadIdx.x;
    const int row0  = blockIdx.x * CHUNK_ROWS;
    const int nrows = (N - row0 < CHUNK_ROWS) ? (N - row0) : CHUNK_ROWS;

    // ---- prologue: 90 parallel row setups (one RCP each, fully overlapped)
    if (tid < nrows) {
        const float2* th = reinterpret_cast<const float2*>(theta)
                           + (size_t)(row0 + tid) * 3;
        const float2 e  = th[0];
        const float2 q0 = th[1];
        const float2 q1 = th[2];
        const float d   = q0.x * q1.y - q0.y * q1.x;
        const float r   = rcp_(d);                    // MUFU.RCP
        const float u01 = -0.5f * (q0.y + q1.x);
        const float m0p = q1.y * e.x + u01 * e.y;     // overlap RCP latency
        const float m1p = u01 * e.x + q0.x * e.y;
        const float inv = -0.5f * r;                  // = -1/(2d)
        const float s00 = q1.y * inv;
        const float s11 = q0.x * inv;
        const float s01 = u01  * inv;
        const float mu0 = m0p * inv;
        const float mu1 = m1p * inv;
        spA[tid] = make_float4(s00, s11, mu0 * SQRT_HL2E, mu1 * SQRT_HL2E);
        spB[tid] = make_float2(-(s01 * s01), s01 + s01);
    }
    __syncthreads();

    if (tid >= ACTIVE) return;
    const int r_local = tid / GROUPS;             // 0..9
    const int g       = tid - r_local * GROUPS;   // 0..24

    // ---- one-time: cache this thread's 4 basis entries in registers ----
    const float4* bm = reinterpret_cast<const float4*>(basis_mu) + 2 * g;
    const float4  m01 = bm[0];
    const float4  m23 = bm[1];
    const float4* bs = reinterpret_cast<const float4*>(basis_sigma) + 4 * g;
    const float4  sg0 = bs[0], sg1 = bs[1], sg2 = bs[2], sg3 = bs[3];

    // basis means pre-scaled by sqrt(K) and negated (dx' = mu0' + nbm0')
    const float nbm0[4] = {-m01.x * SQRT_HL2E, -m01.z * SQRT_HL2E,
                           -m23.x * SQRT_HL2E, -m23.z * SQRT_HL2E};
    const float nbm1[4] = {-m01.y * SQRT_HL2E, -m01.w * SQRT_HL2E,
                           -m23.y * SQRT_HL2E, -m23.w * SQRT_HL2E};
    const float av[4]   = {sg0.x, sg1.x, sg2.x, sg3.x};   // diag var_x
    const float bv[4]   = {sg0.w, sg1.w, sg2.w, sg3.w};   // diag var_y

    for (int rr = r_local; rr < nrows; rr += ROWS_ITER) {
        // per-row params: LDS.128 + LDS.64 broadcast
        const float4 A = spA[rr];    // s00, s11, mu0', mu1'
        const float2 B = spB[rr];    // ns01q, s01_2

        float res[4];
        #pragma unroll
        for (int k = 0; k < 4; ++k) {
            const float c00 = A.x + av[k];
            const float c11 = A.y + bv[k];
            const float dx  = A.z + nbm0[k];          // pre-scaled by sqrt(K)
            const float dy  = A.w + nbm1[k];
            const float det = fmaf(c00, c11, B.x);
            const float rs  = rsqrtf(det);            // MUFU.RSQ in flight
            const float t     = B.y * dy;
            const float inner = fmaf(c11, dx, -t);    // c11*dx' - 2*s01*dy'
            const float v     = dx * inner;
            const float u     = c00 * dy;
            const float num   = fmaf(u, dy, v);       // = K * true quad num
            const float m1    = num * rs;
            const float arg   = m1 * (-rs);           // -K*quad/det
            const float scl   = rs * INV_TWO_PI;      // FMUL-imm
            res[k] = ex2_(arg) * scl;                 // MUFU.EX2
        }
        float4 v4 = make_float4(res[0], res[1], res[2], res[3]);
        *reinterpret_cast<float4*>(out + (size_t)(row0 + rr) * M_CONST + 4 * g) = v4;
    }
}

extern "C" void kernel_launch(void* const* d_in, const int* in_sizes, int n_in,
                              void* d_out, int out_size) {
    const float* theta       = (const float*)d_in[0];
    const float* basis_mu    = (const float*)d_in[1];
    const float* basis_sigma = (const float*)d_in[2];
    float* out = (float*)d_out;

    const int N = in_sizes[0] / 6;

    const int threads = 256;
    const int blocks  = (N + CHUNK_ROWS - 1) / CHUNK_ROWS;
    ContinuousSoftmax_kernel<<<blocks, threads>>>(theta, basis_mu, basis_sigma,
                                                  out, N);
}

// round 13
// speedup vs baseline: 1.9500x; 1.0917x over previous
#include <cuda_runtime.h>
#include <cuda_bf16.h>
#include <cstdint>

#define M_CONST    100
#define GROUPS     25     // M/4 float4 groups per row
#define ROWS_ITER  10     // row slots (250 active threads)
#define ACTIVE     (GROUPS * ROWS_ITER)
#define CHUNK_ROWS 120    // contiguous rows per block (3 pair-iterations)
#define PAIR_STRIDE (2 * ROWS_ITER)

__device__ __forceinline__ float ex2_(float x) {
    float r; asm("ex2.approx.f32 %0, %1;" : "=f"(r) : "f"(x)); return r;
}
__device__ __forceinline__ float rcp_(float x) {
    float r; asm("rcp.approx.f32 %0, %1;" : "=f"(r) : "f"(x)); return r;
}

#define SQRT_HL2E  0.8493218002880191f   // sqrt(0.5*log2(e)) folded into dx,dy
#define INV_TWO_PI 0.15915494309189535f

// basis_sigma is diagonal (reference: vmap(diag)(var)).
// Per-row setup hoisted to a block prologue (one RCP per row, all parallel).
// Hot loop: TWO independent rows per iteration -> 8 interleaved
// det->RSQ->num->EX2 chains per thread per iteration.
__global__ __launch_bounds__(256) void ContinuousSoftmax_kernel(
    const float* __restrict__ theta,        // [N,6]
    const float* __restrict__ basis_mu,     // [M,2]
    const float* __restrict__ basis_sigma,  // [M,2,2] diagonal
    float* __restrict__ out,                // [N,M]
    int N)
{
    __shared__ float4 spA[CHUNK_ROWS];   // s00, s11, mu0', mu1'
    __shared__ float2 spB[CHUNK_ROWS];   // ns01q, s01_2

    const int tid   = threadIdx.x;
    const int row0  = blockIdx.x * CHUNK_ROWS;
    const int nrows = (N - row0 < CHUNK_ROWS) ? (N - row0) : CHUNK_ROWS;

    // ---- prologue: parallel row setups (one MUFU.RCP each) ----
    if (tid < nrows) {
        const float2* th = reinterpret_cast<const float2*>(theta)
                           + (size_t)(row0 + tid) * 3;
        const float2 e  = th[0];
        const float2 q0 = th[1];
        const float2 q1 = th[2];
        const float d   = q0.x * q1.y - q0.y * q1.x;
        const float r   = rcp_(d);                    // MUFU.RCP
        const float u01 = -0.5f * (q0.y + q1.x);
        const float m0p = q1.y * e.x + u01 * e.y;     // overlap RCP latency
        const float m1p = u01 * e.x + q0.x * e.y;
        const float inv = -0.5f * r;                  // = -1/(2d)
        const float s00 = q1.y * inv;
        const float s11 = q0.x * inv;
        const float s01 = u01  * inv;
        const float mu0 = m0p * inv;
        const float mu1 = m1p * inv;
        spA[tid] = make_float4(s00, s11, mu0 * SQRT_HL2E, mu1 * SQRT_HL2E);
        spB[tid] = make_float2(-(s01 * s01), s01 + s01);
    }
    __syncthreads();

    if (tid >= ACTIVE) return;
    const int r_local = tid / GROUPS;             // 0..9
    const int g       = tid - r_local * GROUPS;   // 0..24

    // ---- one-time: cache this thread's 4 basis entries in registers ----
    const float4* bm = reinterpret_cast<const float4*>(basis_mu) + 2 * g;
    const float4  m01 = bm[0];
    const float4  m23 = bm[1];
    const float4* bs = reinterpret_cast<const float4*>(basis_sigma) + 4 * g;
    const float4  sg0 = bs[0], sg1 = bs[1], sg2 = bs[2], sg3 = bs[3];

    // basis means pre-scaled by sqrt(K) and negated (dx' = mu0' + nbm0')
    const float nbm0[4] = {-m01.x * SQRT_HL2E, -m01.z * SQRT_HL2E,
                           -m23.x * SQRT_HL2E, -m23.z * SQRT_HL2E};
    const float nbm1[4] = {-m01.y * SQRT_HL2E, -m01.w * SQRT_HL2E,
                           -m23.y * SQRT_HL2E, -m23.w * SQRT_HL2E};
    const float av[4]   = {sg0.x, sg1.x, sg2.x, sg3.x};   // diag var_x
    const float bv[4]   = {sg0.w, sg1.w, sg2.w, sg3.w};   // diag var_y

    for (int rr = r_local; rr < nrows; rr += PAIR_STRIDE) {
        const int  rB   = rr + ROWS_ITER;
        const bool hasB = (rB < nrows);
        const int  rBc  = hasB ? rB : rr;     // clamp: compute is redundant,
                                              // store is guarded
        const float4 A0 = spA[rr];            // LDS.128 broadcast
        const float2 C0 = spB[rr];
        const float4 A1 = spA[rBc];
        const float2 C1 = spB[rBc];

        float resA[4], resB[4];
        #pragma unroll
        for (int k = 0; k < 4; ++k) {
            // row A chain
            const float a_c00 = A0.x + av[k];
            const float a_c11 = A0.y + bv[k];
            const float a_dx  = A0.z + nbm0[k];
            const float a_dy  = A0.w + nbm1[k];
            const float a_det = fmaf(a_c00, a_c11, C0.x);
            const float a_rs  = rsqrtf(a_det);           // MUFU.RSQ
            // row B chain (independent: fills A's RSQ shadow)
            const float b_c00 = A1.x + av[k];
            const float b_c11 = A1.y + bv[k];
            const float b_dx  = A1.z + nbm0[k];
            const float b_dy  = A1.w + nbm1[k];
            const float b_det = fmaf(b_c00, b_c11, C1.x);
            const float b_rs  = rsqrtf(b_det);

            // numerators overlap the RSQ latencies
            const float a_in  = fmaf(a_c11, a_dx, -(C0.y * a_dy));
            const float a_num = fmaf(a_c00 * a_dy, a_dy, a_dx * a_in);
            const float b_in  = fmaf(b_c11, b_dx, -(C1.y * b_dy));
            const float b_num = fmaf(b_c00 * b_dy, b_dy, b_dx * b_in);

            const float a_r2  = a_rs * a_rs;             // parallel w/ num
            const float b_r2  = b_rs * b_rs;
            const float a_arg = a_num * (-a_r2);
            const float b_arg = b_num * (-b_r2);
            resA[k] = ex2_(a_arg) * (a_rs * INV_TWO_PI); // MUFU.EX2
            resB[k] = ex2_(b_arg) * (b_rs * INV_TWO_PI);
        }
        *reinterpret_cast<float4*>(out + (size_t)(row0 + rr) * M_CONST + 4 * g)
            = make_float4(resA[0], resA[1], resA[2], resA[3]);
        if (hasB)
            *reinterpret_cast<float4*>(out + (size_t)(row0 + rB) * M_CONST + 4 * g)
                = make_float4(resB[0], resB[1], resB[2], resB[3]);
    }
}

extern "C" void kernel_launch(void* const* d_in, const int* in_sizes, int n_in,
                              void* d_out, int out_size) {
    const float* theta       = (const float*)d_in[0];
    const float* basis_mu    = (const float*)d_in[1];
    const float* basis_sigma = (const float*)d_in[2];
    float* out = (float*)d_out;

    const int N = in_sizes[0] / 6;

    const int threads = 256;
    const int blocks  = (N + CHUNK_ROWS - 1) / CHUNK_ROWS;
    ContinuousSoftmax_kernel<<<blocks, threads>>>(theta, basis_mu, basis_sigma,
                                                  out, N);
}